// round 15
// baseline (speedup 1.0000x reference)
#include <cuda_runtime.h>
#include <cuda_fp16.h>
#include <math.h>

#define NN      100000   // nodes
#define HID     64
#define NL      40
#define NNZ_MAX 2500000  // feature nonzeros
#define NE_MAX  1700000  // edges incl self loops
#define SCAN_N  (2 * NN)
#define NF      2048

// ---------------- scratch (no allocations allowed) ----------------
__device__ __align__(256) __half g_W1h[NF * HID];  // fp16 copy of W1
__device__ __align__(256) __half g_hh [NN * HID];  // layer-1 activations (fp16)
__device__ __align__(256) float  g_h2 [NN * HID];  // propagated activations
__device__ __align__(256) float  g_z  [NN * NL];   // dense-layer output

__device__ int  g_cnt[SCAN_N];      // per-row counts (f rows | e rows)
__device__ int  g_off[SCAN_N];      // per-row segment begin
__device__ int  g_cur[SCAN_N];      // fill cursor; after fill == segment end
__device__ int  g_counter[2];       // unordered base allocators (f, e)
__device__ __align__(16) int2 g_fcv[NNZ_MAX];  // (col, val-bits) feature rowsegs
__device__ __align__(16) int2 g_ecv[NE_MAX];   // (col, weight-bits) edge rowsegs

// ---------------- CSR build ----------------

__global__ void k_zero() {
    int i = blockIdx.x * blockDim.x + threadIdx.x;
    if (i < SCAN_N) g_cnt[i] = 0;
    if (i < 2) g_counter[i] = 0;
}

// per-section count
__global__ void k_count(const int* __restrict__ rows, int n, int base) {
    int i = blockIdx.x * blockDim.x + threadIdx.x;
    if (i < n) atomicAdd(&g_cnt[base + rows[i]], 1);
}

// Per-block scan + one atomic base per block. Row ordering in the value
// arrays is arbitrary; only disjoint contiguous per-row segments matter.
__global__ void k_offsets(int sec) {
    __shared__ int s[2][1024];
    __shared__ int sbase;
    int tid = threadIdx.x;
    int gid = blockIdx.x * 1024 + tid;
    int idx = sec * NN + gid;
    int v = (gid < NN) ? g_cnt[idx] : 0;
    int buf = 0;
    s[0][tid] = v; __syncthreads();
#pragma unroll
    for (int o = 1; o < 1024; o <<= 1) {
        int nb = buf ^ 1;
        s[nb][tid] = s[buf][tid] + (tid >= o ? s[buf][tid - o] : 0);
        buf = nb; __syncthreads();
    }
    int incl = s[buf][tid];
    if (tid == 1023) sbase = atomicAdd(&g_counter[sec], incl);
    __syncthreads();
    if (gid < NN) {
        int o = sbase + incl - v;
        g_off[idx] = o;
        g_cur[idx] = o;
    }
}

// 4 strided elements per thread; per-section fill.
__global__ void k_fill_f(const int* __restrict__ frow, const int* __restrict__ fcol,
                         const float* __restrict__ fval, int nnz) {
    int t  = blockIdx.x * blockDim.x + threadIdx.x;
    int Tf = (nnz + 3) >> 2;
    if (t >= Tf) return;
#pragma unroll
    for (int u = 0; u < 4; u++) {
        int k = t + u * Tf;
        if (k < nnz) {
            int r = frow[k];
            int pos = atomicAdd(&g_cur[r], 1);
            g_fcv[pos] = make_int2(fcol[k], __float_as_int(fval[k]));
        }
    }
}

__global__ void k_fill_e(const int* __restrict__ erow, const int* __restrict__ ecol,
                         const float* __restrict__ ew, int ne) {
    int t  = blockIdx.x * blockDim.x + threadIdx.x;
    int Te = (ne + 3) >> 2;
    if (t >= Te) return;
#pragma unroll
    for (int u = 0; u < 4; u++) {
        int k = t + u * Te;
        if (k < ne) {
            int r = erow[k];
            int pos = atomicAdd(&g_cur[NN + r], 1);
            g_ecv[pos] = make_int2(ecol[k], __float_as_int(ew[k]));
        }
    }
}

// W1 -> fp16 (float2 -> half2)
__global__ void k_convW1(const float* __restrict__ W1) {
    int i = blockIdx.x * blockDim.x + threadIdx.x;
    if (i < NF * HID / 2) {
        float2 v = reinterpret_cast<const float2*>(W1)[i];
        reinterpret_cast<__half2*>(g_W1h)[i] = __float22half2_rn(v);
    }
}

// ---------------- forward pass ----------------

// h[row] = b1 + sum_p val_p * W1[col_p]   (warp per row, half2 per lane)
__global__ void __launch_bounds__(256) k_feat_gather(const float* __restrict__ b1) {
    int gid = blockIdx.x * blockDim.x + threadIdx.x;
    int row = gid >> 5;
    int lane = threadIdx.x & 31;
    if (row >= NN) return;
    int beg = g_off[row], end = g_cur[row];
    float2 acc = reinterpret_cast<const float2*>(b1)[lane];
#pragma unroll 8
    for (int p = beg; p < end; p++) {
        int2 cv = g_fcv[p];
        float v = __int_as_float(cv.y);
        __half2 wh = reinterpret_cast<const __half2*>(g_W1h + (size_t)cv.x * HID)[lane];
        float2 w = __half22float2(wh);
        acc.x += v * w.x;
        acc.y += v * w.y;
    }
    reinterpret_cast<__half2*>(g_hh + (size_t)row * HID)[lane] = __float22half2_rn(acc);
}

// h2[row] = sum_e w_e * h[col_e]   (warp per row, half2 per lane, fp32 accum)
__global__ void __launch_bounds__(256) k_edge_gather() {
    int gid = blockIdx.x * blockDim.x + threadIdx.x;
    int row = gid >> 5;
    int lane = threadIdx.x & 31;
    if (row >= NN) return;
    int beg = g_off[NN + row], end = g_cur[NN + row];
    float2 acc = make_float2(0.f, 0.f);
#pragma unroll 8
    for (int p = beg; p < end; p++) {
        int2 cv = g_ecv[p];
        float w = __int_as_float(cv.y);
        __half2 hh = reinterpret_cast<const __half2*>(g_hh + (size_t)cv.x * HID)[lane];
        float2 h = __half22float2(hh);
        acc.x += w * h.x;
        acc.y += w * h.y;
    }
    *reinterpret_cast<float2*>(g_h2 + (size_t)row * HID + 2 * lane) = acc;
}

// z = relu(h2) @ W2 + b2   (one thread per node; W2 in shared as float4)
__global__ void __launch_bounds__(256) k_dense(const float* __restrict__ W2,
                                               const float* __restrict__ b2) {
    __shared__ float4 sW[HID * NL / 4];   // [t][j4] (W2 row-major)
    __shared__ float  sb[NL];
    for (int i = threadIdx.x; i < HID * NL / 4; i += blockDim.x)
        sW[i] = reinterpret_cast<const float4*>(W2)[i];
    if (threadIdx.x < NL) sb[threadIdx.x] = b2[threadIdx.x];
    __syncthreads();

    int node = blockIdx.x * blockDim.x + threadIdx.x;
    if (node >= NN) return;

    float acc[NL];
#pragma unroll
    for (int j = 0; j < NL; j++) acc[j] = sb[j];

    const float4* hrow = reinterpret_cast<const float4*>(g_h2 + (size_t)node * HID);
#pragma unroll
    for (int t4 = 0; t4 < HID / 4; t4++) {
        float4 h4 = hrow[t4];
        float hv[4] = {fmaxf(h4.x, 0.f), fmaxf(h4.y, 0.f), fmaxf(h4.z, 0.f), fmaxf(h4.w, 0.f)};
#pragma unroll
        for (int u = 0; u < 4; u++) {
            int t = t4 * 4 + u;
#pragma unroll
            for (int j4 = 0; j4 < NL / 4; j4++) {
                float4 w = sW[t * (NL / 4) + j4];
                acc[4 * j4 + 0] += hv[u] * w.x;
                acc[4 * j4 + 1] += hv[u] * w.y;
                acc[4 * j4 + 2] += hv[u] * w.z;
                acc[4 * j4 + 3] += hv[u] * w.w;
            }
        }
    }
    float* zrow = g_z + (size_t)node * NL;
#pragma unroll
    for (int j4 = 0; j4 < NL / 4; j4++)
        reinterpret_cast<float4*>(zrow)[j4] =
            make_float4(acc[4*j4], acc[4*j4+1], acc[4*j4+2], acc[4*j4+3]);
}

// out[row] = log_softmax(sum_e w_e * z[col_e])   (warp per row, fused)
__global__ void __launch_bounds__(256) k_zq(float* __restrict__ out) {
    int tid = threadIdx.x;
    int warp = tid >> 5, lane = tid & 31;
    int row = blockIdx.x * 8 + warp;
    if (row >= NN) return;
    int beg = g_off[NN + row], end = g_cur[NN + row];

    float a0 = 0.f, a1 = 0.f;
#pragma unroll 4
    for (int p = beg; p < end; p++) {
        int2 cv = g_ecv[p];
        float w = __int_as_float(cv.y);
        const float* zr = g_z + (size_t)cv.x * NL;
        a0 += w * zr[lane];
        if (lane < NL - 32) a1 += w * zr[32 + lane];
    }

    float v1 = (lane < NL - 32) ? a1 : -1e30f;
    float m = fmaxf(a0, v1);
#pragma unroll
    for (int o = 16; o > 0; o >>= 1) m = fmaxf(m, __shfl_xor_sync(0xffffffffu, m, o));
    float s = __expf(a0 - m) + ((lane < NL - 32) ? __expf(a1 - m) : 0.f);
#pragma unroll
    for (int o = 16; o > 0; o >>= 1) s += __shfl_xor_sync(0xffffffffu, s, o);
    float l = m + logf(s);

    float* orow = out + (size_t)row * NL;
    orow[lane] = a0 - l;
    if (lane < NL - 32) orow[32 + lane] = a1 - l;
}

// ---------------- launch ----------------
extern "C" void kernel_launch(void* const* d_in, const int* in_sizes, int n_in,
                              void* d_out, int out_size) {
    const int*   fidx = (const int*)  d_in[0];   // int32
    const float* fval = (const float*)d_in[1];
    const int*   eidx = (const int*)  d_in[2];   // int32
    const float* ew   = (const float*)d_in[3];
    const float* W1   = (const float*)d_in[4];
    const float* b1   = (const float*)d_in[5];
    const float* W2   = (const float*)d_in[6];
    const float* b2   = (const float*)d_in[7];
    float* out = (float*)d_out;

    int nnz = in_sizes[0] / 2;   // feature_indices is [2, NNZ]
    int ne  = in_sizes[2] / 2;   // edge_indices is [2, E]

    const int* frow = fidx;
    const int* fcol = fidx + nnz;
    const int* erow = eidx;
    const int* ecol = eidx + ne;

    // one-time stream/event setup (host-side resources, not device memory)
    static cudaStream_t sB = nullptr;
    static cudaEvent_t evZero = nullptr, evConv = nullptr, evEdge = nullptr;
    if (!sB) {
        cudaStreamCreateWithFlags(&sB, cudaStreamNonBlocking);
        cudaEventCreateWithFlags(&evZero, cudaEventDisableTiming);
        cudaEventCreateWithFlags(&evConv, cudaEventDisableTiming);
        cudaEventCreateWithFlags(&evEdge, cudaEventDisableTiming);
    }

    // --- zero counters (both sections) on main stream ---
    k_zero<<<(SCAN_N + 255) / 256, 256>>>();
    cudaEventRecord(evZero, 0);

    // --- stream B: W1 conversion + edge CSR build ---
    cudaStreamWaitEvent(sB, evZero, 0);
    k_convW1<<<(NF * HID / 2 + 255) / 256, 256, 0, sB>>>(W1);
    cudaEventRecord(evConv, sB);
    k_count<<<(ne + 255) / 256, 256, 0, sB>>>(erow, ne, NN);
    k_offsets<<<(NN + 1023) / 1024, 1024, 0, sB>>>(1);
    {
        int Te = (ne + 3) >> 2;
        k_fill_e<<<(Te + 255) / 256, 256, 0, sB>>>(erow, ecol, ew, ne);
    }
    cudaEventRecord(evEdge, sB);

    // --- main stream: feature CSR build + feat gather ---
    k_count<<<(nnz + 255) / 256, 256>>>(frow, nnz, 0);
    k_offsets<<<(NN + 1023) / 1024, 1024>>>(0);
    {
        int Tf = (nnz + 3) >> 2;
        k_fill_f<<<(Tf + 255) / 256, 256>>>(frow, fcol, fval, nnz);
    }
    cudaStreamWaitEvent(0, evConv, 0);
    k_feat_gather<<<(NN * 32 + 255) / 256, 256>>>(b1);

    // --- join: rest of forward pass ---
    cudaStreamWaitEvent(0, evEdge, 0);
    k_edge_gather<<<(NN * 32 + 255) / 256, 256>>>();
    k_dense<<<(NN + 255) / 256, 256>>>(W2, b2);
    k_zq<<<(NN + 7) / 8, 256>>>(out);
}

// round 17
// speedup vs baseline: 1.3212x; 1.3212x over previous
#include <cuda_runtime.h>
#include <cuda_fp16.h>
#include <math.h>

#define NN      100000   // nodes
#define HID     64
#define NL      40
#define NNZ_MAX 2500000  // feature nonzeros
#define NE_MAX  1700000  // edges incl self loops
#define SCAN_N  (2 * NN)
#define NF      2048

// ---------------- scratch (no allocations allowed) ----------------
__device__ __align__(256) __half g_W1h[NF * HID];  // fp16 copy of W1
__device__ __align__(256) __half g_hh [NN * HID];  // layer-1 activations (fp16)
__device__ __align__(256) float  g_h2 [NN * HID];  // propagated activations
__device__ __align__(256) float  g_z  [NN * NL];   // dense-layer output

__device__ int  g_cnt[SCAN_N];      // per-row counts (f rows | e rows)
__device__ int  g_off[SCAN_N];      // per-row segment begin
__device__ int  g_cur[SCAN_N];      // fill cursor; after fill == segment end
__device__ int  g_counter[2];       // unordered base allocators (f, e)
__device__ __align__(16) int2 g_fcv[NNZ_MAX];  // (col, val-bits) feature rowsegs
__device__ __align__(16) int2 g_ecv[NE_MAX];   // (col, weight-bits) edge rowsegs

// ---------------- CSR build ----------------

// zero counters + convert W1 to fp16 in one launch
__global__ void k_zero_conv(const float* __restrict__ W1) {
    int i = blockIdx.x * blockDim.x + threadIdx.x;
    if (i < SCAN_N) g_cnt[i] = 0;
    if (i < 2) g_counter[i] = 0;
    if (i < NF * HID / 2) {
        float2 v = reinterpret_cast<const float2*>(W1)[i];
        reinterpret_cast<__half2*>(g_W1h)[i] = __float22half2_rn(v);
    }
}

__global__ void k_count(const int* __restrict__ frow, const int* __restrict__ erow,
                        int nnz, int ne) {
    int i = blockIdx.x * blockDim.x + threadIdx.x;
    if (i < nnz)            atomicAdd(&g_cnt[frow[i]], 1);
    else if (i < nnz + ne)  atomicAdd(&g_cnt[NN + erow[i - nnz]], 1);
}

// Per-block scan + one atomic base per block. Row ordering in the value
// arrays is arbitrary; only disjoint contiguous per-row segments matter.
__global__ void k_offsets() {
    __shared__ int s[2][1024];
    __shared__ int sbase;
    int tid = threadIdx.x;
    int sec = blockIdx.y;                 // 0 = features, 1 = edges
    int gid = blockIdx.x * 1024 + tid;
    int idx = sec * NN + gid;
    int v = (gid < NN) ? g_cnt[idx] : 0;
    int buf = 0;
    s[0][tid] = v; __syncthreads();
#pragma unroll
    for (int o = 1; o < 1024; o <<= 1) {
        int nb = buf ^ 1;
        s[nb][tid] = s[buf][tid] + (tid >= o ? s[buf][tid - o] : 0);
        buf = nb; __syncthreads();
    }
    int incl = s[buf][tid];
    if (tid == 1023) sbase = atomicAdd(&g_counter[sec], incl);
    __syncthreads();
    if (gid < NN) {
        int o = sbase + incl - v;
        g_off[idx] = o;
        g_cur[idx] = o;
    }
}

// 4 strided elements per thread: independent atomic->store chains, coalesced reads.
__global__ void k_fill(const int* __restrict__ frow, const int* __restrict__ fcol,
                       const float* __restrict__ fval,
                       const int* __restrict__ erow, const int* __restrict__ ecol,
                       const float* __restrict__ ew, int nnz, int ne) {
    int t  = blockIdx.x * blockDim.x + threadIdx.x;
    int Tf = (nnz + 3) >> 2;
    int Te = (ne  + 3) >> 2;
    if (t < Tf) {
#pragma unroll
        for (int u = 0; u < 4; u++) {
            int k = t + u * Tf;
            if (k < nnz) {
                int r = frow[k];
                int pos = atomicAdd(&g_cur[r], 1);
                g_fcv[pos] = make_int2(fcol[k], __float_as_int(fval[k]));
            }
        }
    } else if (t < Tf + Te) {
        int i = t - Tf;
#pragma unroll
        for (int u = 0; u < 4; u++) {
            int k = i + u * Te;
            if (k < ne) {
                int r = erow[k];
                int pos = atomicAdd(&g_cur[NN + r], 1);
                g_ecv[pos] = make_int2(ecol[k], __float_as_int(ew[k]));
            }
        }
    }
}

// ---------------- forward pass ----------------

// h[row] = b1 + sum_p val_p * W1[col_p]   (warp per row, half2 per lane)
__global__ void __launch_bounds__(256) k_feat_gather(const float* __restrict__ b1) {
    int gid = blockIdx.x * blockDim.x + threadIdx.x;
    int row = gid >> 5;
    int lane = threadIdx.x & 31;
    if (row >= NN) return;
    int beg = g_off[row], end = g_cur[row];
    float2 acc = reinterpret_cast<const float2*>(b1)[lane];
#pragma unroll 8
    for (int p = beg; p < end; p++) {
        int2 cv = g_fcv[p];
        float v = __int_as_float(cv.y);
        __half2 wh = reinterpret_cast<const __half2*>(g_W1h + (size_t)cv.x * HID)[lane];
        float2 w = __half22float2(wh);
        acc.x += v * w.x;
        acc.y += v * w.y;
    }
    reinterpret_cast<__half2*>(g_hh + (size_t)row * HID)[lane] = __float22half2_rn(acc);
}

// h2[row] = sum_e w_e * h[col_e]   (warp per row, half2 per lane, fp32 accum)
__global__ void __launch_bounds__(256) k_edge_gather() {
    int gid = blockIdx.x * blockDim.x + threadIdx.x;
    int row = gid >> 5;
    int lane = threadIdx.x & 31;
    if (row >= NN) return;
    int beg = g_off[NN + row], end = g_cur[NN + row];
    float2 acc = make_float2(0.f, 0.f);
#pragma unroll 8
    for (int p = beg; p < end; p++) {
        int2 cv = g_ecv[p];
        float w = __int_as_float(cv.y);
        __half2 hh = reinterpret_cast<const __half2*>(g_hh + (size_t)cv.x * HID)[lane];
        float2 h = __half22float2(hh);
        acc.x += w * h.x;
        acc.y += w * h.y;
    }
    *reinterpret_cast<float2*>(g_h2 + (size_t)row * HID + 2 * lane) = acc;
}

// z = relu(h2) @ W2 + b2   (one thread per node; W2 in shared as float4)
__global__ void __launch_bounds__(256) k_dense(const float* __restrict__ W2,
                                               const float* __restrict__ b2) {
    __shared__ float4 sW[HID * NL / 4];   // [t][j4] (W2 row-major)
    __shared__ float  sb[NL];
    for (int i = threadIdx.x; i < HID * NL / 4; i += blockDim.x)
        sW[i] = reinterpret_cast<const float4*>(W2)[i];
    if (threadIdx.x < NL) sb[threadIdx.x] = b2[threadIdx.x];
    __syncthreads();

    int node = blockIdx.x * blockDim.x + threadIdx.x;
    if (node >= NN) return;

    float acc[NL];
#pragma unroll
    for (int j = 0; j < NL; j++) acc[j] = sb[j];

    const float4* hrow = reinterpret_cast<const float4*>(g_h2 + (size_t)node * HID);
#pragma unroll
    for (int t4 = 0; t4 < HID / 4; t4++) {
        float4 h4 = hrow[t4];
        float hv[4] = {fmaxf(h4.x, 0.f), fmaxf(h4.y, 0.f), fmaxf(h4.z, 0.f), fmaxf(h4.w, 0.f)};
#pragma unroll
        for (int u = 0; u < 4; u++) {
            int t = t4 * 4 + u;
#pragma unroll
            for (int j4 = 0; j4 < NL / 4; j4++) {
                float4 w = sW[t * (NL / 4) + j4];
                acc[4 * j4 + 0] += hv[u] * w.x;
                acc[4 * j4 + 1] += hv[u] * w.y;
                acc[4 * j4 + 2] += hv[u] * w.z;
                acc[4 * j4 + 3] += hv[u] * w.w;
            }
        }
    }
    float* zrow = g_z + (size_t)node * NL;
#pragma unroll
    for (int j4 = 0; j4 < NL / 4; j4++)
        reinterpret_cast<float4*>(zrow)[j4] =
            make_float4(acc[4*j4], acc[4*j4+1], acc[4*j4+2], acc[4*j4+3]);
}

// out[row] = log_softmax(sum_e w_e * z[col_e])   (warp per row, fused)
__global__ void __launch_bounds__(256) k_zq(float* __restrict__ out) {
    int tid = threadIdx.x;
    int warp = tid >> 5, lane = tid & 31;
    int row = blockIdx.x * 8 + warp;
    if (row >= NN) return;
    int beg = g_off[NN + row], end = g_cur[NN + row];

    float a0 = 0.f, a1 = 0.f;
#pragma unroll 4
    for (int p = beg; p < end; p++) {
        int2 cv = g_ecv[p];
        float w = __int_as_float(cv.y);
        const float* zr = g_z + (size_t)cv.x * NL;
        a0 += w * zr[lane];
        if (lane < NL - 32) a1 += w * zr[32 + lane];
    }

    float v1 = (lane < NL - 32) ? a1 : -1e30f;
    float m = fmaxf(a0, v1);
#pragma unroll
    for (int o = 16; o > 0; o >>= 1) m = fmaxf(m, __shfl_xor_sync(0xffffffffu, m, o));
    float s = __expf(a0 - m) + ((lane < NL - 32) ? __expf(a1 - m) : 0.f);
#pragma unroll
    for (int o = 16; o > 0; o >>= 1) s += __shfl_xor_sync(0xffffffffu, s, o);
    float l = m + logf(s);

    float* orow = out + (size_t)row * NL;
    orow[lane] = a0 - l;
    if (lane < NL - 32) orow[32 + lane] = a1 - l;
}

// ---------------- launch ----------------
extern "C" void kernel_launch(void* const* d_in, const int* in_sizes, int n_in,
                              void* d_out, int out_size) {
    const int*   fidx = (const int*)  d_in[0];   // int32
    const float* fval = (const float*)d_in[1];
    const int*   eidx = (const int*)  d_in[2];   // int32
    const float* ew   = (const float*)d_in[3];
    const float* W1   = (const float*)d_in[4];
    const float* b1   = (const float*)d_in[5];
    const float* W2   = (const float*)d_in[6];
    const float* b2   = (const float*)d_in[7];
    float* out = (float*)d_out;

    int nnz = in_sizes[0] / 2;   // feature_indices is [2, NNZ]
    int ne  = in_sizes[2] / 2;   // edge_indices is [2, E]

    const int* frow = fidx;
    const int* fcol = fidx + nnz;
    const int* erow = eidx;
    const int* ecol = eidx + ne;
    int tot = nnz + ne;

    // --- CSR build (unordered row placement) ---
    k_zero_conv<<<(SCAN_N + 255) / 256, 256>>>(W1);   // SCAN_N > NF*HID/2 covers conv
    k_count<<<(tot + 255) / 256, 256>>>(frow, erow, nnz, ne);
    {
        dim3 grid((NN + 1023) / 1024, 2);
        k_offsets<<<grid, 1024>>>();
    }
    {
        int threads = ((nnz + 3) >> 2) + ((ne + 3) >> 2);
        k_fill<<<(threads + 255) / 256, 256>>>(frow, fcol, fval, erow, ecol, ew, nnz, ne);
    }

    // --- forward pass ---
    k_feat_gather<<<(NN * 32 + 255) / 256, 256>>>(b1);
    k_edge_gather<<<(NN * 32 + 255) / 256, 256>>>();
    k_dense<<<(NN + 255) / 256, 256>>>(W2, b2);
    k_zq<<<(NN + 7) / 8, 256>>>(out);
}